// round 2
// baseline (speedup 1.0000x reference)
#include <cuda_runtime.h>
#include <cuda_bf16.h>
#include <cstdint>

// Problem constants
#define NN 50000
#define EE 800000
#define HH 4

// -------- scratch pool (device global, no allocations) --------
// layout (floats):
//   feat  : NN*256
//   bufA  : NN*256
//   bufB  : NN*256
//   el    : NN*4
//   er    : NN*4
//   emax  : NN*4   (as unsigned keys)
//   denom : NN*4
//   earr  : EE*4
__device__ float g_pool[(size_t)NN * 256 * 3 + (size_t)NN * 4 * 4 + (size_t)EE * 4];

// monotone float->uint key for atomicMax over floats
__device__ __forceinline__ unsigned fkey(float f) {
    unsigned b = __float_as_uint(f);
    return (b & 0x80000000u) ? ~b : (b | 0x80000000u);
}
__device__ __forceinline__ float fdecode(unsigned k) {
    unsigned b = (k & 0x80000000u) ? (k ^ 0x80000000u) : ~k;
    return __uint_as_float(b);
}

// -------- zero kernel --------
__global__ void zero_kernel(float* p, int n) {
    int t = blockIdx.x * blockDim.x + threadIdx.x;
    if (t < n) p[t] = 0.0f;
}

// -------- 64x64 tiled SGEMM: C[M,Ncols] = A[M,K] * B[K,Ncols] --------
// K must be a multiple of 16 (K=256 here). Handles M/Ncols tails.
__global__ void sgemm64(const float* __restrict__ A, const float* __restrict__ B,
                        float* __restrict__ C, int M, int K, int Ncols) {
    __shared__ float As[16][64 + 2];
    __shared__ float Bs[16][64 + 2];
    int tid = threadIdx.x;                 // 256 threads
    int tx = tid & 15;                     // 0..15
    int ty = tid >> 4;                     // 0..15
    int rowBase = blockIdx.y * 64;
    int colBase = blockIdx.x * 64;

    int aRow = tid >> 2;                   // 0..63
    int aK0  = (tid & 3) * 4;              // 0,4,8,12
    int bK   = tid >> 4;                   // 0..15
    int bC0  = (tid & 15) * 4;             // 0..60

    float acc[4][4] = {};

    for (int kk = 0; kk < K; kk += 16) {
        // A tile (64 rows x 16 k), store transposed
        float4 av = make_float4(0.f, 0.f, 0.f, 0.f);
        int gr = rowBase + aRow;
        if (gr < M)
            av = *reinterpret_cast<const float4*>(&A[(size_t)gr * K + kk + aK0]);
        As[aK0 + 0][aRow] = av.x;
        As[aK0 + 1][aRow] = av.y;
        As[aK0 + 2][aRow] = av.z;
        As[aK0 + 3][aRow] = av.w;

        // B tile (16 k x 64 cols)
        int gc = colBase + bC0;
        float4 bv;
        if (gc + 3 < Ncols) {
            bv = *reinterpret_cast<const float4*>(&B[(size_t)(kk + bK) * Ncols + gc]);
        } else {
            float t0 = (gc + 0 < Ncols) ? B[(size_t)(kk + bK) * Ncols + gc + 0] : 0.f;
            float t1 = (gc + 1 < Ncols) ? B[(size_t)(kk + bK) * Ncols + gc + 1] : 0.f;
            float t2 = (gc + 2 < Ncols) ? B[(size_t)(kk + bK) * Ncols + gc + 2] : 0.f;
            float t3 = (gc + 3 < Ncols) ? B[(size_t)(kk + bK) * Ncols + gc + 3] : 0.f;
            bv = make_float4(t0, t1, t2, t3);
        }
        Bs[bK][bC0 + 0] = bv.x;
        Bs[bK][bC0 + 1] = bv.y;
        Bs[bK][bC0 + 2] = bv.z;
        Bs[bK][bC0 + 3] = bv.w;

        __syncthreads();
#pragma unroll
        for (int k = 0; k < 16; k++) {
            float ra[4], rb[4];
#pragma unroll
            for (int i = 0; i < 4; i++) ra[i] = As[k][ty * 4 + i];
#pragma unroll
            for (int j = 0; j < 4; j++) rb[j] = Bs[k][tx * 4 + j];
#pragma unroll
            for (int i = 0; i < 4; i++)
#pragma unroll
                for (int j = 0; j < 4; j++) acc[i][j] += ra[i] * rb[j];
        }
        __syncthreads();
    }

#pragma unroll
    for (int i = 0; i < 4; i++) {
        int r = rowBase + ty * 4 + i;
        if (r >= M) continue;
#pragma unroll
        for (int j = 0; j < 4; j++) {
            int c = colBase + tx * 4 + j;
            if (c < Ncols) C[(size_t)r * Ncols + c] = acc[i][j];
        }
    }
}

// -------- per (node, head) attention dot products --------
__global__ void el_er_kernel(const float* __restrict__ feat,
                             const float* __restrict__ al, const float* __restrict__ ar,
                             float* __restrict__ el, float* __restrict__ er,
                             int N, int D) {
    int w = (blockIdx.x * blockDim.x + threadIdx.x) >> 5;
    int lane = threadIdx.x & 31;
    if (w >= N * HH) return;
    int n = w / HH, h = w - n * HH;
    const float* f = feat + (size_t)n * HH * D + h * D;
    float sl = 0.f, sr = 0.f;
    for (int d = lane; d < D; d += 32) {
        float fv = f[d];
        sl += fv * al[h * D + d];
        sr += fv * ar[h * D + d];
    }
#pragma unroll
    for (int o = 16; o; o >>= 1) {
        sl += __shfl_down_sync(0xffffffffu, sl, o);
        sr += __shfl_down_sync(0xffffffffu, sr, o);
    }
    if (lane == 0) { el[w] = sl; er[w] = sr; }
}

// -------- edge pass 0: e = leaky_relu(el[src]+er[dst]); segment max over dst --------
__global__ void edge_e_max(const int* __restrict__ src, const int* __restrict__ dst,
                           const float* __restrict__ el, const float* __restrict__ er,
                           float* __restrict__ e_out, unsigned* __restrict__ emax, int E) {
    int t = blockIdx.x * blockDim.x + threadIdx.x;
    if (t >= E * HH) return;
    int ed = t >> 2, h = t & 3;
    int s = src[ed], d0 = dst[ed];
    float v = el[s * HH + h] + er[d0 * HH + h];
    v = (v > 0.f) ? v : 0.2f * v;
    e_out[t] = v;
    atomicMax(&emax[d0 * HH + h], fkey(v));
}

// -------- edge pass A: ee = exp(e - emax[dst]); segment sum --------
__global__ void edge_exp_sum(const int* __restrict__ dst, float* __restrict__ e_io,
                             const unsigned* __restrict__ emax, float* __restrict__ denom, int E) {
    int t = blockIdx.x * blockDim.x + threadIdx.x;
    if (t >= E * HH) return;
    int ed = t >> 2, h = t & 3;
    int d0 = dst[ed];
    float m = fdecode(emax[d0 * HH + h]);
    float ee = __expf(e_io[t] - m);
    e_io[t] = ee;
    atomicAdd(&denom[d0 * HH + h], ee);
}

// -------- edge pass B: out[dst] += alpha * feat[src]  (one warp per edge) --------
__global__ void edge_aggregate(const int* __restrict__ src, const int* __restrict__ dst,
                               const float* __restrict__ ee, const float* __restrict__ denom,
                               const float* __restrict__ feat, float* __restrict__ out,
                               int E, int D) {
    int w = (blockIdx.x * blockDim.x + threadIdx.x) >> 5;
    int lane = threadIdx.x & 31;
    if (w >= E) return;
    int s = src[w], d0 = dst[w];
    int HD = HH * D;
    float a[HH];
#pragma unroll
    for (int h = 0; h < HH; h++)
        a[h] = ee[w * HH + h] / fmaxf(denom[d0 * HH + h], 1e-9f);
    const float* fs = feat + (size_t)s * HD;
    float* od = out + (size_t)d0 * HD;
    for (int i = lane; i < HD; i += 32) {
        int h = i / D;
        atomicAdd(&od[i], a[h] * fs[i]);
    }
}

// -------- epilogue: out = elu(out + b) --------
__global__ void bias_elu(float* __restrict__ out, const float* __restrict__ b, int total, int HD) {
    int t = blockIdx.x * blockDim.x + threadIdx.x;
    if (t >= total) return;
    int c = t % HD;
    float v = out[t] + b[c];
    out[t] = (v > 0.f) ? v : expm1f(v);
}

// -------- final: logits[n,c] = mean_h(agg[n,h,c] + b2[h,c]) --------
__global__ void final_mean(const float* __restrict__ agg, const float* __restrict__ b2,
                           float* __restrict__ logits, int N) {
    int t = blockIdx.x * blockDim.x + threadIdx.x;
    if (t >= N * 40) return;
    int n = t / 40, c = t - n * 40;
    float s = 0.f;
#pragma unroll
    for (int h = 0; h < HH; h++)
        s += agg[(size_t)n * 160 + h * 40 + c] + b2[h * 40 + c];
    logits[t] = s * 0.25f;
}

// ---------------------------------------------------------------
extern "C" void kernel_launch(void* const* d_in, const int* in_sizes, int n_in,
                              void* d_out, int out_size) {
    const float* x  = (const float*)d_in[0];
    const int*   ei = (const int*)d_in[1];
    const float* W0  = (const float*)d_in[2];
    const float* al0 = (const float*)d_in[3];
    const float* ar0 = (const float*)d_in[4];
    const float* b0  = (const float*)d_in[5];
    const float* W1  = (const float*)d_in[6];
    const float* al1 = (const float*)d_in[7];
    const float* ar1 = (const float*)d_in[8];
    const float* b1  = (const float*)d_in[9];
    const float* W2  = (const float*)d_in[10];
    const float* al2 = (const float*)d_in[11];
    const float* ar2 = (const float*)d_in[12];
    const float* b2  = (const float*)d_in[13];

    int E = in_sizes[1] / 2;
    int N = in_sizes[0] / 256;
    const int* src = ei;
    const int* dst = ei + E;

    void* poolv = nullptr;
    cudaGetSymbolAddress(&poolv, g_pool);
    float* pool = (float*)poolv;
    float*    feat  = pool;
    float*    bufA  = feat  + (size_t)NN * 256;
    float*    bufB  = bufA  + (size_t)NN * 256;
    float*    el    = bufB  + (size_t)NN * 256;
    float*    er    = el    + (size_t)NN * 4;
    unsigned* emax  = (unsigned*)(er + (size_t)NN * 4);
    float*    denom = (float*)emax + (size_t)NN * 4;
    float*    earr  = denom + (size_t)NN * 4;

    const int TB = 256;
    auto blocks = [](long n, int tb) { return (int)((n + tb - 1) / tb); };

    auto run_layer = [&](const float* in, const float* W, const float* al, const float* ar,
                         int D, float* outbuf) {
        int HD = HH * D;
        // clear segment buffers + output accumulator
        zero_kernel<<<blocks((long)N * HD, TB), TB>>>(outbuf, N * HD);
        zero_kernel<<<blocks((long)N * HH * 2, TB), TB>>>((float*)emax, N * HH * 2); // emax+denom adjacent
        // feat = in @ W
        dim3 g((HD + 63) / 64, (N + 63) / 64);
        sgemm64<<<g, 256>>>(in, W, feat, N, 256, HD);
        // el / er
        el_er_kernel<<<blocks((long)N * HH * 32, TB), TB>>>(feat, al, ar, el, er, N, D);
        // edge softmax
        edge_e_max<<<blocks((long)E * HH, TB), TB>>>(src, dst, el, er, earr, emax, E);
        edge_exp_sum<<<blocks((long)E * HH, TB), TB>>>(dst, earr, emax, denom, E);
        // aggregate
        edge_aggregate<<<blocks((long)E * 32, TB), TB>>>(src, dst, earr, denom, feat, outbuf, E, D);
    };

    // Layer 0: x -> bufA
    run_layer(x, W0, al0, ar0, 64, bufA);
    bias_elu<<<blocks((long)N * 256, TB), TB>>>(bufA, b0, N * 256, 256);

    // Layer 1: bufA -> bufB
    run_layer(bufA, W1, al1, ar1, 64, bufB);
    bias_elu<<<blocks((long)N * 256, TB), TB>>>(bufB, b1, N * 256, 256);

    // Layer 2: bufB -> bufA (HD=160)
    run_layer(bufB, W2, al2, ar2, 40, bufA);

    // mean over heads -> logits
    final_mean<<<blocks((long)N * 40, TB), TB>>>(bufA, b2, (float*)d_out, N);
}

// round 3
// speedup vs baseline: 1.7350x; 1.7350x over previous
#include <cuda_runtime.h>
#include <cuda_bf16.h>
#include <cstdint>

#define NN 50000
#define EE 800000
#define HH 4

// -------- scratch (device globals, no allocations) --------
// floats: feat NN*256 | bufA NN*256 | bufB NN*256 | el NN*4 | er NN*4
__device__ float g_pool[(size_t)NN * 256 * 3 + (size_t)NN * 8];
// ints: rowptr NN+1 | deg NN | cursor NN | srcSorted EE
__device__ int g_ipool[(size_t)NN * 3 + 1 + (size_t)EE];

// -------- CSR build --------
__global__ void zero_int(int* p, int n) {
    int t = blockIdx.x * blockDim.x + threadIdx.x;
    if (t < n) p[t] = 0;
}
__global__ void hist_kernel(const int* __restrict__ dst, int* __restrict__ deg, int E) {
    int t = blockIdx.x * blockDim.x + threadIdx.x;
    if (t < E) atomicAdd(&deg[dst[t]], 1);
}
__global__ void scan_kernel(const int* __restrict__ deg, int* __restrict__ rowptr, int N, int E) {
    __shared__ int sums[1024];
    int t = threadIdx.x;
    int chunk = (N + 1023) >> 10;
    int lo = t * chunk, hi = min(N, lo + chunk);
    int s = 0;
    for (int i = lo; i < hi; i++) s += deg[i];
    sums[t] = s;
    __syncthreads();
    for (int off = 1; off < 1024; off <<= 1) {
        int v = (t >= off) ? sums[t - off] : 0;
        __syncthreads();
        sums[t] += v;
        __syncthreads();
    }
    int run = (t == 0) ? 0 : sums[t - 1];
    for (int i = lo; i < hi; i++) { rowptr[i] = run; run += deg[i]; }
    if (lo < N && hi == N) rowptr[N] = E;
}
__global__ void copy_int(const int* __restrict__ a, int* __restrict__ b, int n) {
    int t = blockIdx.x * blockDim.x + threadIdx.x;
    if (t < n) b[t] = a[t];
}
__global__ void scatter_kernel(const int* __restrict__ src, const int* __restrict__ dst,
                               int* __restrict__ cursor, int* __restrict__ srcSorted, int E) {
    int t = blockIdx.x * blockDim.x + threadIdx.x;
    if (t >= E) return;
    int d = dst[t];
    int pos = atomicAdd(&cursor[d], 1);
    srcSorted[pos] = src[t];
}

// -------- 128x128 tiled SGEMM, K-panel 16, 8x8 per thread --------
__global__ __launch_bounds__(256) void sgemm128(const float* __restrict__ A,
                                                const float* __restrict__ B,
                                                float* __restrict__ C,
                                                int M, int K, int Ncols) {
    __shared__ float As[16][128];
    __shared__ float Bs[16][128];
    int tid = threadIdx.x;
    int tx = tid & 15, ty = tid >> 4;
    int rowBase = blockIdx.y * 128;
    int colBase = blockIdx.x * 128;

    int ar = tid >> 1;             // 0..127
    int ak = (tid & 1) * 8;        // 0 or 8
    int br = tid >> 4;             // 0..15
    int bc = (tid & 15) * 8;       // 0..120

    float acc[8][8] = {};

    for (int kk = 0; kk < K; kk += 16) {
        // load A tile (128 rows x 16 k), transposed into As[k][m]
        int gr = rowBase + ar;
        float4 a0 = make_float4(0.f, 0.f, 0.f, 0.f), a1 = a0;
        if (gr < M) {
            const float* ap = &A[(size_t)gr * K + kk + ak];
            a0 = *reinterpret_cast<const float4*>(ap);
            a1 = *reinterpret_cast<const float4*>(ap + 4);
        }
        As[ak + 0][ar] = a0.x; As[ak + 1][ar] = a0.y;
        As[ak + 2][ar] = a0.z; As[ak + 3][ar] = a0.w;
        As[ak + 4][ar] = a1.x; As[ak + 5][ar] = a1.y;
        As[ak + 6][ar] = a1.z; As[ak + 7][ar] = a1.w;

        // load B tile (16 k x 128 cols)
        int gc = colBase + bc;
        float4 b0 = make_float4(0.f, 0.f, 0.f, 0.f), b1 = b0;
        if (gc + 7 < Ncols) {
            const float* bp = &B[(size_t)(kk + br) * Ncols + gc];
            b0 = *reinterpret_cast<const float4*>(bp);
            b1 = *reinterpret_cast<const float4*>(bp + 4);
        }
        *reinterpret_cast<float4*>(&Bs[br][bc]) = b0;
        *reinterpret_cast<float4*>(&Bs[br][bc + 4]) = b1;

        __syncthreads();
#pragma unroll
        for (int k = 0; k < 16; k++) {
            float4 ra0 = *reinterpret_cast<const float4*>(&As[k][ty * 8]);
            float4 ra1 = *reinterpret_cast<const float4*>(&As[k][ty * 8 + 4]);
            float4 rb0 = *reinterpret_cast<const float4*>(&Bs[k][tx * 8]);
            float4 rb1 = *reinterpret_cast<const float4*>(&Bs[k][tx * 8 + 4]);
            float ra[8] = {ra0.x, ra0.y, ra0.z, ra0.w, ra1.x, ra1.y, ra1.z, ra1.w};
            float rb[8] = {rb0.x, rb0.y, rb0.z, rb0.w, rb1.x, rb1.y, rb1.z, rb1.w};
#pragma unroll
            for (int i = 0; i < 8; i++)
#pragma unroll
                for (int j = 0; j < 8; j++) acc[i][j] += ra[i] * rb[j];
        }
        __syncthreads();
    }

#pragma unroll
    for (int i = 0; i < 8; i++) {
        int r = rowBase + ty * 8 + i;
        if (r >= M) continue;
#pragma unroll
        for (int j = 0; j < 8; j += 4) {
            int c = colBase + tx * 8 + j;
            if (c + 3 < Ncols) {
                float4 v = make_float4(acc[i][j], acc[i][j + 1], acc[i][j + 2], acc[i][j + 3]);
                *reinterpret_cast<float4*>(&C[(size_t)r * Ncols + c]) = v;
            }
        }
    }
}

// -------- per (node, head) attention dot products --------
__global__ void el_er_kernel(const float* __restrict__ feat,
                             const float* __restrict__ al, const float* __restrict__ ar,
                             float* __restrict__ el, float* __restrict__ er,
                             int N, int D) {
    int w = (blockIdx.x * blockDim.x + threadIdx.x) >> 5;
    int lane = threadIdx.x & 31;
    if (w >= N * HH) return;
    int n = w / HH, h = w - n * HH;
    const float* f = feat + (size_t)n * HH * D + h * D;
    float sl = 0.f, sr = 0.f;
    for (int d = lane; d < D; d += 32) {
        float fv = f[d];
        sl += fv * al[h * D + d];
        sr += fv * ar[h * D + d];
    }
#pragma unroll
    for (int o = 16; o; o >>= 1) {
        sl += __shfl_down_sync(0xffffffffu, sl, o);
        sr += __shfl_down_sync(0xffffffffu, sr, o);
    }
    if (lane == 0) { el[w] = sl; er[w] = sr; }
}

// -------- fused softmax + aggregation: one warp per dst node --------
// MODE 0: D=64, out[d,256] = elu(acc/denom + bias)
// MODE 1: D=40, out[d,160] = acc/denom + bias   (mean over heads done after)
template <int D, int MODE>
__global__ __launch_bounds__(256) void gat_aggregate(
    const int* __restrict__ rowptr, const int* __restrict__ srcS,
    const float* __restrict__ el, const float* __restrict__ er,
    const float* __restrict__ feat, const float* __restrict__ bias,
    float* __restrict__ out, int N) {
    constexpr int HD = 4 * D;
    constexpr int CPL = HD / 32;   // 8 (D=64) or 5 (D=40)
    __shared__ float sEE[8][4][32];
    __shared__ int sSrc[8][32];
    int wl = threadIdx.x >> 5, lane = threadIdx.x & 31;
    int d = blockIdx.x * 8 + wl;
    if (d >= N) return;
    int begin = rowptr[d], end = rowptr[d + 1];

    float4 erv = *reinterpret_cast<const float4*>(&er[d * 4]);
    float er4[4] = {erv.x, erv.y, erv.z, erv.w};

    // pass 1: per-head max (lane-parallel over edges)
    float m[4] = {-1e30f, -1e30f, -1e30f, -1e30f};
    for (int i = begin + lane; i < end; i += 32) {
        int s = srcS[i];
        float4 e4 = *reinterpret_cast<const float4*>(&el[s * 4]);
        float v;
        v = e4.x + er4[0]; v = v > 0.f ? v : 0.2f * v; m[0] = fmaxf(m[0], v);
        v = e4.y + er4[1]; v = v > 0.f ? v : 0.2f * v; m[1] = fmaxf(m[1], v);
        v = e4.z + er4[2]; v = v > 0.f ? v : 0.2f * v; m[2] = fmaxf(m[2], v);
        v = e4.w + er4[3]; v = v > 0.f ? v : 0.2f * v; m[3] = fmaxf(m[3], v);
    }
#pragma unroll
    for (int h = 0; h < 4; h++)
#pragma unroll
        for (int o = 16; o; o >>= 1)
            m[h] = fmaxf(m[h], __shfl_xor_sync(0xffffffffu, m[h], o));

    // pass 2: exp + weighted aggregation
    float acc[CPL];
#pragma unroll
    for (int j = 0; j < CPL; j++) acc[j] = 0.f;
    float den[4] = {0.f, 0.f, 0.f, 0.f};

    for (int base = begin; base < end; base += 32) {
        int cnt = min(32, end - base);
        if (lane < cnt) {
            int s = srcS[base + lane];
            sSrc[wl][lane] = s;
            float4 e4 = *reinterpret_cast<const float4*>(&el[s * 4]);
            float v, ee;
            v = e4.x + er4[0]; v = v > 0.f ? v : 0.2f * v; ee = __expf(v - m[0]); den[0] += ee; sEE[wl][0][lane] = ee;
            v = e4.y + er4[1]; v = v > 0.f ? v : 0.2f * v; ee = __expf(v - m[1]); den[1] += ee; sEE[wl][1][lane] = ee;
            v = e4.z + er4[2]; v = v > 0.f ? v : 0.2f * v; ee = __expf(v - m[2]); den[2] += ee; sEE[wl][2][lane] = ee;
            v = e4.w + er4[3]; v = v > 0.f ? v : 0.2f * v; ee = __expf(v - m[3]); den[3] += ee; sEE[wl][3][lane] = ee;
        }
        __syncwarp();
        for (int t = 0; t < cnt; t++) {
            int s = sSrc[wl][t];
            const float* fs = feat + (size_t)s * HD;
            if (D == 64) {
                int h = lane >> 3;                 // 8 contiguous channels per lane, one head
                float ee = sEE[wl][h][t];
                float4 f0 = *reinterpret_cast<const float4*>(&fs[lane * 8]);
                float4 f1 = *reinterpret_cast<const float4*>(&fs[lane * 8 + 4]);
                acc[0] += ee * f0.x; acc[1] += ee * f0.y;
                acc[2] += ee * f0.z; acc[3] += ee * f0.w;
                acc[4] += ee * f1.x; acc[5] += ee * f1.y;
                acc[6] += ee * f1.z; acc[7] += ee * f1.w;
            } else {
                int c0 = lane * 5;
#pragma unroll
                for (int j = 0; j < 5; j++) {
                    int c = c0 + j;
                    acc[j] += sEE[wl][c / 40][t] * fs[c];
                }
            }
        }
        __syncwarp();
    }

    // reduce denom across lanes
#pragma unroll
    for (int h = 0; h < 4; h++) {
#pragma unroll
        for (int o = 16; o; o >>= 1)
            den[h] += __shfl_xor_sync(0xffffffffu, den[h], o);
        den[h] = fmaxf(den[h], 1e-9f);
    }

    if (MODE == 0) {
        int c0 = lane * 8;
        float inv = 1.f / den[lane >> 3];
        float o[8];
#pragma unroll
        for (int j = 0; j < 8; j++) {
            float v = acc[j] * inv + bias[c0 + j];
            o[j] = v > 0.f ? v : expm1f(v);
        }
        float* op = out + (size_t)d * 256 + c0;
        *reinterpret_cast<float4*>(op) = make_float4(o[0], o[1], o[2], o[3]);
        *reinterpret_cast<float4*>(op + 4) = make_float4(o[4], o[5], o[6], o[7]);
    } else {
        int c0 = lane * 5;
#pragma unroll
        for (int j = 0; j < 5; j++) {
            int c = c0 + j;
            out[(size_t)d * 160 + c] = acc[j] / den[c / 40] + bias[c];
        }
    }
}

// -------- final mean over heads (bias already applied) --------
__global__ void final_mean(const float* __restrict__ agg, float* __restrict__ logits, int N) {
    int t = blockIdx.x * blockDim.x + threadIdx.x;
    if (t >= N * 40) return;
    int n = t / 40, c = t - n * 40;
    const float* a = agg + (size_t)n * 160 + c;
    logits[t] = 0.25f * (a[0] + a[40] + a[80] + a[120]);
}

// ---------------------------------------------------------------
extern "C" void kernel_launch(void* const* d_in, const int* in_sizes, int n_in,
                              void* d_out, int out_size) {
    const float* x  = (const float*)d_in[0];
    const int*   ei = (const int*)d_in[1];
    const float* W0  = (const float*)d_in[2];
    const float* al0 = (const float*)d_in[3];
    const float* ar0 = (const float*)d_in[4];
    const float* b0  = (const float*)d_in[5];
    const float* W1  = (const float*)d_in[6];
    const float* al1 = (const float*)d_in[7];
    const float* ar1 = (const float*)d_in[8];
    const float* b1  = (const float*)d_in[9];
    const float* W2  = (const float*)d_in[10];
    const float* al2 = (const float*)d_in[11];
    const float* ar2 = (const float*)d_in[12];
    const float* b2  = (const float*)d_in[13];

    int E = in_sizes[1] / 2;
    int N = in_sizes[0] / 256;
    const int* src = ei;
    const int* dst = ei + E;

    void* pv = nullptr;
    cudaGetSymbolAddress(&pv, g_pool);
    float* pool = (float*)pv;
    float* feat = pool;
    float* bufA = feat + (size_t)NN * 256;
    float* bufB = bufA + (size_t)NN * 256;
    float* el   = bufB + (size_t)NN * 256;
    float* er   = el + (size_t)NN * 4;

    void* iv = nullptr;
    cudaGetSymbolAddress(&iv, g_ipool);
    int* rowptr = (int*)iv;
    int* deg    = rowptr + NN + 1;
    int* cursor = deg + NN;
    int* srcS   = cursor + NN;

    const int TB = 256;
    auto blocks = [](long n, int tb) { return (int)((n + tb - 1) / tb); };

    // ---- build CSR (by dst) ----
    zero_int<<<blocks(N, TB), TB>>>(deg, N);
    hist_kernel<<<blocks(E, TB), TB>>>(dst, deg, E);
    scan_kernel<<<1, 1024>>>(deg, rowptr, N, E);
    copy_int<<<blocks(N, TB), TB>>>(rowptr, cursor, N);
    scatter_kernel<<<blocks(E, TB), TB>>>(src, dst, cursor, srcS, E);

    int aggBlocks = (N + 7) / 8;

    // ---- layer 0: x -> bufA ----
    {
        dim3 g((256 + 127) / 128, (N + 127) / 128);
        sgemm128<<<g, 256>>>(x, W0, feat, N, 256, 256);
        el_er_kernel<<<blocks((long)N * HH * 32, TB), TB>>>(feat, al0, ar0, el, er, N, 64);
        gat_aggregate<64, 0><<<aggBlocks, 256>>>(rowptr, srcS, el, er, feat, b0, bufA, N);
    }
    // ---- layer 1: bufA -> bufB ----
    {
        dim3 g((256 + 127) / 128, (N + 127) / 128);
        sgemm128<<<g, 256>>>(bufA, W1, feat, N, 256, 256);
        el_er_kernel<<<blocks((long)N * HH * 32, TB), TB>>>(feat, al1, ar1, el, er, N, 64);
        gat_aggregate<64, 0><<<aggBlocks, 256>>>(rowptr, srcS, el, er, feat, b1, bufB, N);
    }
    // ---- layer 2: bufB -> bufA (HD=160) ----
    {
        dim3 g((160 + 127) / 128, (N + 127) / 128);
        sgemm128<<<g, 256>>>(bufB, W2, feat, N, 256, 160);
        el_er_kernel<<<blocks((long)N * HH * 32, TB), TB>>>(feat, al2, ar2, el, er, N, 40);
        gat_aggregate<40, 1><<<aggBlocks, 256>>>(rowptr, srcS, el, er, feat, b2, bufA, N);
    }
    final_mean<<<blocks((long)N * 40, TB), TB>>>(bufA, (float*)d_out, N);
}

// round 4
// speedup vs baseline: 2.4299x; 1.4005x over previous
#include <cuda_runtime.h>
#include <cuda_bf16.h>
#include <cstdint>

#define NN 50000
#define EE 800000
#define HH 4

// -------- scratch (device globals, no allocations) --------
__device__ float g_pool[(size_t)NN * 256 * 3 + (size_t)NN * 8];
__device__ int g_ipool[(size_t)NN * 3 + 1 + (size_t)EE];

// -------- CSR build --------
__global__ void zero_int(int* p, int n) {
    int t = blockIdx.x * blockDim.x + threadIdx.x;
    if (t < n) p[t] = 0;
}
__global__ void hist_kernel(const int* __restrict__ dst, int* __restrict__ deg, int E) {
    int t = blockIdx.x * blockDim.x + threadIdx.x;
    if (t < E) atomicAdd(&deg[dst[t]], 1);
}
__global__ void scan_kernel(const int* __restrict__ deg, int* __restrict__ rowptr,
                            int* __restrict__ cursor, int N, int E) {
    __shared__ int sums[1024];
    int t = threadIdx.x;
    int chunk = (N + 1023) >> 10;
    int lo = t * chunk, hi = min(N, lo + chunk);
    int s = 0;
    for (int i = lo; i < hi; i++) s += deg[i];
    sums[t] = s;
    __syncthreads();
    for (int off = 1; off < 1024; off <<= 1) {
        int v = (t >= off) ? sums[t - off] : 0;
        __syncthreads();
        sums[t] += v;
        __syncthreads();
    }
    int run = (t == 0) ? 0 : sums[t - 1];
    for (int i = lo; i < hi; i++) { rowptr[i] = run; cursor[i] = run; run += deg[i]; }
    if (lo < N && hi == N) rowptr[N] = E;
}
__global__ void scatter_kernel(const int* __restrict__ src, const int* __restrict__ dst,
                               int* __restrict__ cursor, int* __restrict__ srcSorted, int E) {
    int t = blockIdx.x * blockDim.x + threadIdx.x;
    if (t >= E) return;
    int d = dst[t];
    int pos = atomicAdd(&cursor[d], 1);
    srcSorted[pos] = src[t];
}

// -------- tf32 tensor-core GEMM: C[M,Ncols] = A[M,K] * B[K,Ncols] --------
// 128x128 block tile, 8 warps in 2x4 grid, 64x32 warp tile = 4x4 m16n8k8 frags.
__device__ __forceinline__ unsigned f2tf32(float f) {
    unsigned r;
    asm("cvt.rna.tf32.f32 %0, %1;" : "=r"(r) : "f"(f));
    return r;
}

#define SM_STRIDE 136   // 136 % 32 == 8 -> conflict-free fragment loads

__global__ __launch_bounds__(256) void gemm_tf32(const float* __restrict__ A,
                                                 const float* __restrict__ B,
                                                 float* __restrict__ C,
                                                 int M, int K, int Ncols) {
    __shared__ unsigned As[16][SM_STRIDE];
    __shared__ unsigned Bs[16][SM_STRIDE];
    int tid = threadIdx.x;
    int warp = tid >> 5, lane = tid & 31;
    int gid = lane >> 2, tig = lane & 3;     // groupID, threadID-in-group
    int warp_m = warp >> 2, warp_n = warp & 3;
    int rowBase = blockIdx.y * 128;
    int colBase = blockIdx.x * 128;

    // global->smem mapping
    int ar = tid >> 1;              // 0..127
    int ak = (tid & 1) * 8;         // 0 / 8
    int br = tid >> 4;              // 0..15
    int bc = (tid & 15) * 8;        // 0..120

    float acc[4][4][4];             // [mi][ni][c0..c3]
#pragma unroll
    for (int i = 0; i < 4; i++)
#pragma unroll
        for (int j = 0; j < 4; j++)
#pragma unroll
            for (int c = 0; c < 4; c++) acc[i][j][c] = 0.f;

    for (int kk = 0; kk < K; kk += 16) {
        // A tile: 128 rows x 16 k, store transposed As[k][m] as tf32
        {
            int gr = rowBase + ar;
            float4 a0 = make_float4(0.f, 0.f, 0.f, 0.f), a1 = a0;
            if (gr < M) {
                const float* ap = &A[(size_t)gr * K + kk + ak];
                a0 = *reinterpret_cast<const float4*>(ap);
                a1 = *reinterpret_cast<const float4*>(ap + 4);
            }
            As[ak + 0][ar] = f2tf32(a0.x); As[ak + 1][ar] = f2tf32(a0.y);
            As[ak + 2][ar] = f2tf32(a0.z); As[ak + 3][ar] = f2tf32(a0.w);
            As[ak + 4][ar] = f2tf32(a1.x); As[ak + 5][ar] = f2tf32(a1.y);
            As[ak + 6][ar] = f2tf32(a1.z); As[ak + 7][ar] = f2tf32(a1.w);
        }
        // B tile: 16 k x 128 cols
        {
            int gc = colBase + bc;
            float v[8];
            if (gc + 7 < Ncols) {
                const float* bp = &B[(size_t)(kk + br) * Ncols + gc];
                float4 b0 = *reinterpret_cast<const float4*>(bp);
                float4 b1 = *reinterpret_cast<const float4*>(bp + 4);
                v[0] = b0.x; v[1] = b0.y; v[2] = b0.z; v[3] = b0.w;
                v[4] = b1.x; v[5] = b1.y; v[6] = b1.z; v[7] = b1.w;
            } else {
#pragma unroll
                for (int j = 0; j < 8; j++)
                    v[j] = (gc + j < Ncols) ? B[(size_t)(kk + br) * Ncols + gc + j] : 0.f;
            }
#pragma unroll
            for (int j = 0; j < 8; j++) Bs[br][bc + j] = f2tf32(v[j]);
        }
        __syncthreads();

#pragma unroll
        for (int ks = 0; ks < 2; ks++) {
            int k0 = ks * 8;
            unsigned af[4][4], bf[4][2];
#pragma unroll
            for (int mi = 0; mi < 4; mi++) {
                int mB = warp_m * 64 + mi * 16;
                af[mi][0] = As[k0 + tig][mB + gid];
                af[mi][1] = As[k0 + tig][mB + gid + 8];
                af[mi][2] = As[k0 + tig + 4][mB + gid];
                af[mi][3] = As[k0 + tig + 4][mB + gid + 8];
            }
#pragma unroll
            for (int ni = 0; ni < 4; ni++) {
                int nB = warp_n * 32 + ni * 8;
                bf[ni][0] = Bs[k0 + tig][nB + gid];
                bf[ni][1] = Bs[k0 + tig + 4][nB + gid];
            }
#pragma unroll
            for (int mi = 0; mi < 4; mi++)
#pragma unroll
                for (int ni = 0; ni < 4; ni++) {
                    asm volatile(
                        "mma.sync.aligned.m16n8k8.row.col.f32.tf32.tf32.f32 "
                        "{%0,%1,%2,%3}, {%4,%5,%6,%7}, {%8,%9}, {%0,%1,%2,%3};\n"
                        : "+f"(acc[mi][ni][0]), "+f"(acc[mi][ni][1]),
                          "+f"(acc[mi][ni][2]), "+f"(acc[mi][ni][3])
                        : "r"(af[mi][0]), "r"(af[mi][1]), "r"(af[mi][2]), "r"(af[mi][3]),
                          "r"(bf[ni][0]), "r"(bf[ni][1]));
                }
        }
        __syncthreads();
    }

    // epilogue: c0/c1 adjacent cols -> float2 stores
#pragma unroll
    for (int mi = 0; mi < 4; mi++) {
        int r0 = rowBase + warp_m * 64 + mi * 16 + gid;
#pragma unroll
        for (int ni = 0; ni < 4; ni++) {
            int c0 = colBase + warp_n * 32 + ni * 8 + tig * 2;
            if (c0 + 1 < Ncols || c0 + 1 == Ncols) {
                if (c0 + 1 < Ncols + 1 && c0 < Ncols) {
                    if (r0 < M)
                        *reinterpret_cast<float2*>(&C[(size_t)r0 * Ncols + c0]) =
                            make_float2(acc[mi][ni][0], acc[mi][ni][1]);
                    if (r0 + 8 < M)
                        *reinterpret_cast<float2*>(&C[(size_t)(r0 + 8) * Ncols + c0]) =
                            make_float2(acc[mi][ni][2], acc[mi][ni][3]);
                }
            }
        }
    }
}

// -------- per (node, head) attention dot products --------
__global__ void el_er_kernel(const float* __restrict__ feat,
                             const float* __restrict__ al, const float* __restrict__ ar,
                             float* __restrict__ el, float* __restrict__ er,
                             int N, int D) {
    int w = (blockIdx.x * blockDim.x + threadIdx.x) >> 5;
    int lane = threadIdx.x & 31;
    if (w >= N * HH) return;
    int n = w / HH, h = w - n * HH;
    const float* f = feat + (size_t)n * HH * D + h * D;
    float sl = 0.f, sr = 0.f;
    for (int d = lane; d < D; d += 32) {
        float fv = f[d];
        sl += fv * al[h * D + d];
        sr += fv * ar[h * D + d];
    }
#pragma unroll
    for (int o = 16; o; o >>= 1) {
        sl += __shfl_down_sync(0xffffffffu, sl, o);
        sr += __shfl_down_sync(0xffffffffu, sr, o);
    }
    if (lane == 0) { el[w] = sl; er[w] = sr; }
}

// -------- fused softmax + aggregation: one warp per dst node --------
template <int D, int MODE>
__global__ __launch_bounds__(256) void gat_aggregate(
    const int* __restrict__ rowptr, const int* __restrict__ srcS,
    const float* __restrict__ el, const float* __restrict__ er,
    const float* __restrict__ feat, const float* __restrict__ bias,
    float* __restrict__ out, int N) {
    constexpr int HD = 4 * D;
    constexpr int CPL = HD / 32;
    __shared__ float sEE[8][4][32];
    __shared__ int sSrc[8][32];
    int wl = threadIdx.x >> 5, lane = threadIdx.x & 31;
    int d = blockIdx.x * 8 + wl;
    if (d >= N) return;
    int begin = rowptr[d], end = rowptr[d + 1];

    float4 erv = *reinterpret_cast<const float4*>(&er[d * 4]);
    float er4[4] = {erv.x, erv.y, erv.z, erv.w};

    float m[4] = {-1e30f, -1e30f, -1e30f, -1e30f};
    for (int i = begin + lane; i < end; i += 32) {
        int s = srcS[i];
        float4 e4 = *reinterpret_cast<const float4*>(&el[s * 4]);
        float v;
        v = e4.x + er4[0]; v = v > 0.f ? v : 0.2f * v; m[0] = fmaxf(m[0], v);
        v = e4.y + er4[1]; v = v > 0.f ? v : 0.2f * v; m[1] = fmaxf(m[1], v);
        v = e4.z + er4[2]; v = v > 0.f ? v : 0.2f * v; m[2] = fmaxf(m[2], v);
        v = e4.w + er4[3]; v = v > 0.f ? v : 0.2f * v; m[3] = fmaxf(m[3], v);
    }
#pragma unroll
    for (int h = 0; h < 4; h++)
#pragma unroll
        for (int o = 16; o; o >>= 1)
            m[h] = fmaxf(m[h], __shfl_xor_sync(0xffffffffu, m[h], o));

    float acc[CPL];
#pragma unroll
    for (int j = 0; j < CPL; j++) acc[j] = 0.f;
    float den[4] = {0.f, 0.f, 0.f, 0.f};

    for (int base = begin; base < end; base += 32) {
        int cnt = min(32, end - base);
        if (lane < cnt) {
            int s = srcS[base + lane];
            sSrc[wl][lane] = s;
            float4 e4 = *reinterpret_cast<const float4*>(&el[s * 4]);
            float v, ee;
            v = e4.x + er4[0]; v = v > 0.f ? v : 0.2f * v; ee = __expf(v - m[0]); den[0] += ee; sEE[wl][0][lane] = ee;
            v = e4.y + er4[1]; v = v > 0.f ? v : 0.2f * v; ee = __expf(v - m[1]); den[1] += ee; sEE[wl][1][lane] = ee;
            v = e4.z + er4[2]; v = v > 0.f ? v : 0.2f * v; ee = __expf(v - m[2]); den[2] += ee; sEE[wl][2][lane] = ee;
            v = e4.w + er4[3]; v = v > 0.f ? v : 0.2f * v; ee = __expf(v - m[3]); den[3] += ee; sEE[wl][3][lane] = ee;
        }
        __syncwarp();
        for (int t = 0; t < cnt; t++) {
            int s = sSrc[wl][t];
            const float* fs = feat + (size_t)s * HD;
            if (D == 64) {
                int h = lane >> 3;
                float ee = sEE[wl][h][t];
                float4 f0 = *reinterpret_cast<const float4*>(&fs[lane * 8]);
                float4 f1 = *reinterpret_cast<const float4*>(&fs[lane * 8 + 4]);
                acc[0] += ee * f0.x; acc[1] += ee * f0.y;
                acc[2] += ee * f0.z; acc[3] += ee * f0.w;
                acc[4] += ee * f1.x; acc[5] += ee * f1.y;
                acc[6] += ee * f1.z; acc[7] += ee * f1.w;
            } else {
                int c0 = lane * 5;
#pragma unroll
                for (int j = 0; j < 5; j++) {
                    int c = c0 + j;
                    acc[j] += sEE[wl][c / 40][t] * fs[c];
                }
            }
        }
        __syncwarp();
    }

#pragma unroll
    for (int h = 0; h < 4; h++) {
#pragma unroll
        for (int o = 16; o; o >>= 1)
            den[h] += __shfl_xor_sync(0xffffffffu, den[h], o);
        den[h] = fmaxf(den[h], 1e-9f);
    }

    if (MODE == 0) {
        int c0 = lane * 8;
        float inv = 1.f / den[lane >> 3];
        float o[8];
#pragma unroll
        for (int j = 0; j < 8; j++) {
            float v = acc[j] * inv + bias[c0 + j];
            o[j] = v > 0.f ? v : expm1f(v);
        }
        float* op = out + (size_t)d * 256 + c0;
        *reinterpret_cast<float4*>(op) = make_float4(o[0], o[1], o[2], o[3]);
        *reinterpret_cast<float4*>(op + 4) = make_float4(o[4], o[5], o[6], o[7]);
    } else {
        int c0 = lane * 5;
#pragma unroll
        for (int j = 0; j < 5; j++) {
            int c = c0 + j;
            out[(size_t)d * 160 + c] = acc[j] / den[c / 40] + bias[c];
        }
    }
}

// -------- final mean over heads (bias already applied) --------
__global__ void final_mean(const float* __restrict__ agg, float* __restrict__ logits, int N) {
    int t = blockIdx.x * blockDim.x + threadIdx.x;
    if (t >= N * 40) return;
    int n = t / 40, c = t - n * 40;
    const float* a = agg + (size_t)n * 160 + c;
    logits[t] = 0.25f * (a[0] + a[40] + a[80] + a[120]);
}

// ---------------------------------------------------------------
extern "C" void kernel_launch(void* const* d_in, const int* in_sizes, int n_in,
                              void* d_out, int out_size) {
    const float* x  = (const float*)d_in[0];
    const int*   ei = (const int*)d_in[1];
    const float* W0  = (const float*)d_in[2];
    const float* al0 = (const float*)d_in[3];
    const float* ar0 = (const float*)d_in[4];
    const float* b0  = (const float*)d_in[5];
    const float* W1  = (const float*)d_in[6];
    const float* al1 = (const float*)d_in[7];
    const float* ar1 = (const float*)d_in[8];
    const float* b1  = (const float*)d_in[9];
    const float* W2  = (const float*)d_in[10];
    const float* al2 = (const float*)d_in[11];
    const float* ar2 = (const float*)d_in[12];
    const float* b2  = (const float*)d_in[13];

    int E = in_sizes[1] / 2;
    int N = in_sizes[0] / 256;
    const int* src = ei;
    const int* dst = ei + E;

    void* pv = nullptr;
    cudaGetSymbolAddress(&pv, g_pool);
    float* pool = (float*)pv;
    float* feat = pool;
    float* bufA = feat + (size_t)NN * 256;
    float* bufB = bufA + (size_t)NN * 256;
    float* el   = bufB + (size_t)NN * 256;
    float* er   = el + (size_t)NN * 4;

    void* iv = nullptr;
    cudaGetSymbolAddress(&iv, g_ipool);
    int* rowptr = (int*)iv;
    int* deg    = rowptr + NN + 1;
    int* cursor = deg + NN;
    int* srcS   = cursor + NN;

    const int TB = 256;
    auto blocks = [](long n, int tb) { return (int)((n + tb - 1) / tb); };

    // ---- build CSR (by dst) ----
    zero_int<<<blocks(N, TB), TB>>>(deg, N);
    hist_kernel<<<blocks(E, TB), TB>>>(dst, deg, E);
    scan_kernel<<<1, 1024>>>(deg, rowptr, cursor, N, E);
    scatter_kernel<<<blocks(E, TB), TB>>>(src, dst, cursor, srcS, E);

    int aggBlocks = (N + 7) / 8;
    int gy = (N + 127) / 128;

    // ---- layer 0 ----
    gemm_tf32<<<dim3(2, gy), 256>>>(x, W0, feat, N, 256, 256);
    el_er_kernel<<<blocks((long)N * HH * 32, TB), TB>>>(feat, al0, ar0, el, er, N, 64);
    gat_aggregate<64, 0><<<aggBlocks, 256>>>(rowptr, srcS, el, er, feat, b0, bufA, N);
    // ---- layer 1 ----
    gemm_tf32<<<dim3(2, gy), 256>>>(bufA, W1, feat, N, 256, 256);
    el_er_kernel<<<blocks((long)N * HH * 32, TB), TB>>>(feat, al1, ar1, el, er, N, 64);
    gat_aggregate<64, 0><<<aggBlocks, 256>>>(rowptr, srcS, el, er, feat, b1, bufB, N);
    // ---- layer 2 (HD=160) ----
    gemm_tf32<<<dim3(2, gy), 256>>>(bufB, W2, feat, N, 256, 160);
    el_er_kernel<<<blocks((long)N * HH * 32, TB), TB>>>(feat, al2, ar2, el, er, N, 40);
    gat_aggregate<40, 1><<<aggBlocks, 256>>>(rowptr, srcS, el, er, feat, b2, bufA, N);

    final_mean<<<blocks((long)N * 40, TB), TB>>>(bufA, (float*)d_out, N);
}

// round 5
// speedup vs baseline: 2.6748x; 1.1008x over previous
#include <cuda_runtime.h>
#include <cuda_bf16.h>
#include <cstdint>

#define NN 50000
#define EE 800000
#define HH 4

// -------- scratch (device globals, no allocations) --------
__device__ float g_pool[(size_t)NN * 256 * 3 + (size_t)NN * 8];
__device__ int g_ipool[(size_t)NN * 3 + 1 + (size_t)EE];

// -------- small utility kernels --------
__global__ void zero_int(int* p, int n) {
    int t = blockIdx.x * blockDim.x + threadIdx.x;
    if (t < n) p[t] = 0;
}
__global__ void zero_f(float* p, int n) {
    int t = blockIdx.x * blockDim.x + threadIdx.x;
    if (t < n) p[t] = 0.f;
}
__global__ void hist_kernel(const int* __restrict__ dst, int* __restrict__ deg, int E) {
    int t = blockIdx.x * blockDim.x + threadIdx.x;
    if (t < E) atomicAdd(&deg[dst[t]], 1);
}
__global__ void scan_kernel(const int* __restrict__ deg, int* __restrict__ rowptr,
                            int* __restrict__ cursor, int N, int E) {
    __shared__ int sums[1024];
    int t = threadIdx.x;
    int chunk = (N + 1023) >> 10;
    int lo = t * chunk, hi = min(N, lo + chunk);
    int s = 0;
    for (int i = lo; i < hi; i++) s += deg[i];
    sums[t] = s;
    __syncthreads();
    for (int off = 1; off < 1024; off <<= 1) {
        int v = (t >= off) ? sums[t - off] : 0;
        __syncthreads();
        sums[t] += v;
        __syncthreads();
    }
    int run = (t == 0) ? 0 : sums[t - 1];
    for (int i = lo; i < hi; i++) { rowptr[i] = run; cursor[i] = run; run += deg[i]; }
    if (lo < N && hi == N) rowptr[N] = E;
}
__global__ void scatter_kernel(const int* __restrict__ src, const int* __restrict__ dst,
                               int* __restrict__ cursor, int* __restrict__ srcSorted, int E) {
    int t = blockIdx.x * blockDim.x + threadIdx.x;
    if (t >= E) return;
    int d = dst[t];
    int pos = atomicAdd(&cursor[d], 1);
    srcSorted[pos] = src[t];
}

// -------- tf32 tensor-core GEMM with register-prefetch pipeline --------
// 128x128 block tile, 8 warps (2x4), 64x32 warp tile = 4x4 m16n8k8 frags.
// ATT=true: also emit el/er = feat . al/ar partials via shuffle+atomicAdd
// (requires 64-wide heads aligned to warp column tiles; layers 0/1 only).
__device__ __forceinline__ unsigned f2tf32(float f) {
    unsigned r;
    asm("cvt.rna.tf32.f32 %0, %1;" : "=r"(r) : "f"(f));
    return r;
}

#define SM_STRIDE 136

template <bool ATT>
__global__ __launch_bounds__(256) void gemm_tf32(const float* __restrict__ A,
                                                 const float* __restrict__ B,
                                                 float* __restrict__ C,
                                                 int M, int K, int Ncols,
                                                 const float* __restrict__ al,
                                                 const float* __restrict__ ar,
                                                 float* __restrict__ el,
                                                 float* __restrict__ er) {
    __shared__ unsigned As[16][SM_STRIDE];
    __shared__ unsigned Bs[16][SM_STRIDE];
    int tid = threadIdx.x;
    int warp = tid >> 5, lane = tid & 31;
    int gid = lane >> 2, tig = lane & 3;
    int warp_m = warp >> 2, warp_n = warp & 3;
    int rowBase = blockIdx.y * 128;
    int colBase = blockIdx.x * 128;

    int ar_ = tid >> 1;             // A row in tile 0..127
    int ak = (tid & 1) * 8;         // 0 / 8
    int br = tid >> 4;              // B k-row 0..15
    int bc = (tid & 15) * 8;        // B col 0..120

    int gr = rowBase + ar_;
    bool aOk = (gr < M);
    int gc = colBase + bc;
    bool bFull = (gc + 7 < Ncols);

    const float* aBase = A + (size_t)gr * K + ak;
    const float* bBase = B + (size_t)br * Ncols + gc;

    float acc[4][4][4];
#pragma unroll
    for (int i = 0; i < 4; i++)
#pragma unroll
        for (int j = 0; j < 4; j++)
#pragma unroll
            for (int c = 0; c < 4; c++) acc[i][j][c] = 0.f;

    const int P = K >> 4;
    float ra[8], rb[8];

    // prologue load panel 0
    {
        if (aOk) {
            float4 a0 = *reinterpret_cast<const float4*>(aBase);
            float4 a1 = *reinterpret_cast<const float4*>(aBase + 4);
            ra[0] = a0.x; ra[1] = a0.y; ra[2] = a0.z; ra[3] = a0.w;
            ra[4] = a1.x; ra[5] = a1.y; ra[6] = a1.z; ra[7] = a1.w;
        } else {
#pragma unroll
            for (int i = 0; i < 8; i++) ra[i] = 0.f;
        }
        if (bFull) {
            float4 b0 = *reinterpret_cast<const float4*>(bBase);
            float4 b1 = *reinterpret_cast<const float4*>(bBase + 4);
            rb[0] = b0.x; rb[1] = b0.y; rb[2] = b0.z; rb[3] = b0.w;
            rb[4] = b1.x; rb[5] = b1.y; rb[6] = b1.z; rb[7] = b1.w;
        } else {
#pragma unroll
            for (int j = 0; j < 8; j++)
                rb[j] = (gc + j < Ncols) ? bBase[j] : 0.f;
        }
    }

    for (int p = 0; p < P; p++) {
        // store current panel to smem (tf32)
#pragma unroll
        for (int i = 0; i < 8; i++) As[ak + i][ar_] = f2tf32(ra[i]);
#pragma unroll
        for (int j = 0; j < 8; j++) Bs[br][bc + j] = f2tf32(rb[j]);
        __syncthreads();

        // prefetch next panel
        float na[8], nb[8];
        if (p + 1 < P) {
            const float* ap = aBase + (p + 1) * 16;
            const float* bp = bBase + (size_t)(p + 1) * 16 * Ncols;
            if (aOk) {
                float4 a0 = *reinterpret_cast<const float4*>(ap);
                float4 a1 = *reinterpret_cast<const float4*>(ap + 4);
                na[0] = a0.x; na[1] = a0.y; na[2] = a0.z; na[3] = a0.w;
                na[4] = a1.x; na[5] = a1.y; na[6] = a1.z; na[7] = a1.w;
            } else {
#pragma unroll
                for (int i = 0; i < 8; i++) na[i] = 0.f;
            }
            if (bFull) {
                float4 b0 = *reinterpret_cast<const float4*>(bp);
                float4 b1 = *reinterpret_cast<const float4*>(bp + 4);
                nb[0] = b0.x; nb[1] = b0.y; nb[2] = b0.z; nb[3] = b0.w;
                nb[4] = b1.x; nb[5] = b1.y; nb[6] = b1.z; nb[7] = b1.w;
            } else {
#pragma unroll
                for (int j = 0; j < 8; j++)
                    nb[j] = (gc + j < Ncols) ? bp[j] : 0.f;
            }
        } else {
#pragma unroll
            for (int i = 0; i < 8; i++) { na[i] = 0.f; nb[i] = 0.f; }
        }

        // compute
#pragma unroll
        for (int ks = 0; ks < 2; ks++) {
            int k0 = ks * 8;
            unsigned af[4][4], bf[4][2];
#pragma unroll
            for (int mi = 0; mi < 4; mi++) {
                int mB = warp_m * 64 + mi * 16;
                af[mi][0] = As[k0 + tig][mB + gid];
                af[mi][1] = As[k0 + tig][mB + gid + 8];
                af[mi][2] = As[k0 + tig + 4][mB + gid];
                af[mi][3] = As[k0 + tig + 4][mB + gid + 8];
            }
#pragma unroll
            for (int ni = 0; ni < 4; ni++) {
                int nB = warp_n * 32 + ni * 8;
                bf[ni][0] = Bs[k0 + tig][nB + gid];
                bf[ni][1] = Bs[k0 + tig + 4][nB + gid];
            }
#pragma unroll
            for (int mi = 0; mi < 4; mi++)
#pragma unroll
                for (int ni = 0; ni < 4; ni++) {
                    asm volatile(
                        "mma.sync.aligned.m16n8k8.row.col.f32.tf32.tf32.f32 "
                        "{%0,%1,%2,%3}, {%4,%5,%6,%7}, {%8,%9}, {%0,%1,%2,%3};\n"
                        : "+f"(acc[mi][ni][0]), "+f"(acc[mi][ni][1]),
                          "+f"(acc[mi][ni][2]), "+f"(acc[mi][ni][3])
                        : "r"(af[mi][0]), "r"(af[mi][1]), "r"(af[mi][2]), "r"(af[mi][3]),
                          "r"(bf[ni][0]), "r"(bf[ni][1]));
                }
        }
        __syncthreads();
#pragma unroll
        for (int i = 0; i < 8; i++) { ra[i] = na[i]; rb[i] = nb[i]; }
    }

    // store C
#pragma unroll
    for (int mi = 0; mi < 4; mi++) {
        int r0 = rowBase + warp_m * 64 + mi * 16 + gid;
#pragma unroll
        for (int ni = 0; ni < 4; ni++) {
            int c0 = colBase + warp_n * 32 + ni * 8 + tig * 2;
            if (c0 < Ncols) {
                if (r0 < M)
                    *reinterpret_cast<float2*>(&C[(size_t)r0 * Ncols + c0]) =
                        make_float2(acc[mi][ni][0], acc[mi][ni][1]);
                if (r0 + 8 < M)
                    *reinterpret_cast<float2*>(&C[(size_t)(r0 + 8) * Ncols + c0]) =
                        make_float2(acc[mi][ni][2], acc[mi][ni][3]);
            }
        }
    }

    // fused el/er partials (heads are 64 cols wide; warp cols lie in one head)
    if (ATT) {
        int h = (colBase + warp_n * 32) >> 6;
#pragma unroll
        for (int mi = 0; mi < 4; mi++) {
            float pl0 = 0.f, pl1 = 0.f, pr0 = 0.f, pr1 = 0.f;
#pragma unroll
            for (int ni = 0; ni < 4; ni++) {
#pragma unroll
                for (int j = 0; j < 2; j++) {
                    int cw = (colBase + warp_n * 32 + ni * 8 + tig * 2 + j) & 63;
                    float av = al[h * 64 + cw];
                    float rv = ar[h * 64 + cw];
                    pl0 += acc[mi][ni][j] * av;
                    pr0 += acc[mi][ni][j] * rv;
                    pl1 += acc[mi][ni][2 + j] * av;
                    pr1 += acc[mi][ni][2 + j] * rv;
                }
            }
#pragma unroll
            for (int o = 1; o <= 2; o <<= 1) {
                pl0 += __shfl_xor_sync(0xffffffffu, pl0, o);
                pr0 += __shfl_xor_sync(0xffffffffu, pr0, o);
                pl1 += __shfl_xor_sync(0xffffffffu, pl1, o);
                pr1 += __shfl_xor_sync(0xffffffffu, pr1, o);
            }
            if (tig == 0) {
                int r0 = rowBase + warp_m * 64 + mi * 16 + gid;
                if (r0 < M) {
                    atomicAdd(&el[r0 * 4 + h], pl0);
                    atomicAdd(&er[r0 * 4 + h], pr0);
                }
                if (r0 + 8 < M) {
                    atomicAdd(&el[(r0 + 8) * 4 + h], pl1);
                    atomicAdd(&er[(r0 + 8) * 4 + h], pr1);
                }
            }
        }
    }
}

// -------- el/er for layer 2 (D=40, heads unaligned) --------
__global__ void el_er_kernel(const float* __restrict__ feat,
                             const float* __restrict__ al, const float* __restrict__ ar,
                             float* __restrict__ el, float* __restrict__ er,
                             int N, int D) {
    int w = (blockIdx.x * blockDim.x + threadIdx.x) >> 5;
    int lane = threadIdx.x & 31;
    if (w >= N * HH) return;
    int n = w / HH, h = w - n * HH;
    const float* f = feat + (size_t)n * HH * D + h * D;
    float sl = 0.f, sr = 0.f;
    for (int d = lane; d < D; d += 32) {
        float fv = f[d];
        sl += fv * al[h * D + d];
        sr += fv * ar[h * D + d];
    }
#pragma unroll
    for (int o = 16; o; o >>= 1) {
        sl += __shfl_down_sync(0xffffffffu, sl, o);
        sr += __shfl_down_sync(0xffffffffu, sr, o);
    }
    if (lane == 0) { el[w] = sl; er[w] = sr; }
}

// -------- fused softmax + aggregation: one warp per dst node --------
// MODE 0: D=64, out[d,256] = elu(acc/denom + bias)
// MODE 1: D=40, out = logits[d,40] = mean_h(acc/denom + bias)
template <int D, int MODE>
__global__ __launch_bounds__(256) void gat_aggregate(
    const int* __restrict__ rowptr, const int* __restrict__ srcS,
    const float* __restrict__ el, const float* __restrict__ er,
    const float* __restrict__ feat, const float* __restrict__ bias,
    float* __restrict__ out, int N) {
    constexpr int HD = 4 * D;
    constexpr int CPL = HD / 32;
    __shared__ float sEE[8][4][32];
    __shared__ int sSrc[8][32];
    __shared__ float sOut[MODE == 1 ? 8 : 1][MODE == 1 ? 160 : 1];
    int wl = threadIdx.x >> 5, lane = threadIdx.x & 31;
    int d = blockIdx.x * 8 + wl;
    if (d >= N) return;
    int begin = rowptr[d], end = rowptr[d + 1];

    float4 erv = *reinterpret_cast<const float4*>(&er[d * 4]);
    float er4[4] = {erv.x, erv.y, erv.z, erv.w};

    float m[4] = {-1e30f, -1e30f, -1e30f, -1e30f};
    for (int i = begin + lane; i < end; i += 32) {
        int s = srcS[i];
        float4 e4 = *reinterpret_cast<const float4*>(&el[s * 4]);
        float v;
        v = e4.x + er4[0]; v = v > 0.f ? v : 0.2f * v; m[0] = fmaxf(m[0], v);
        v = e4.y + er4[1]; v = v > 0.f ? v : 0.2f * v; m[1] = fmaxf(m[1], v);
        v = e4.z + er4[2]; v = v > 0.f ? v : 0.2f * v; m[2] = fmaxf(m[2], v);
        v = e4.w + er4[3]; v = v > 0.f ? v : 0.2f * v; m[3] = fmaxf(m[3], v);
    }
#pragma unroll
    for (int h = 0; h < 4; h++)
#pragma unroll
        for (int o = 16; o; o >>= 1)
            m[h] = fmaxf(m[h], __shfl_xor_sync(0xffffffffu, m[h], o));

    float acc[CPL];
#pragma unroll
    for (int j = 0; j < CPL; j++) acc[j] = 0.f;
    float den[4] = {0.f, 0.f, 0.f, 0.f};

    for (int base = begin; base < end; base += 32) {
        int cnt = min(32, end - base);
        if (lane < cnt) {
            int s = srcS[base + lane];
            sSrc[wl][lane] = s;
            float4 e4 = *reinterpret_cast<const float4*>(&el[s * 4]);
            float v, ee;
            v = e4.x + er4[0]; v = v > 0.f ? v : 0.2f * v; ee = __expf(v - m[0]); den[0] += ee; sEE[wl][0][lane] = ee;
            v = e4.y + er4[1]; v = v > 0.f ? v : 0.2f * v; ee = __expf(v - m[1]); den[1] += ee; sEE[wl][1][lane] = ee;
            v = e4.z + er4[2]; v = v > 0.f ? v : 0.2f * v; ee = __expf(v - m[2]); den[2] += ee; sEE[wl][2][lane] = ee;
            v = e4.w + er4[3]; v = v > 0.f ? v : 0.2f * v; ee = __expf(v - m[3]); den[3] += ee; sEE[wl][3][lane] = ee;
        }
        __syncwarp();

        if (D == 64) {
            int h = lane >> 3;
            int t = 0;
            for (; t + 1 < cnt; t += 2) {
                int s0 = sSrc[wl][t], s1 = sSrc[wl][t + 1];
                float ee0 = sEE[wl][h][t], ee1 = sEE[wl][h][t + 1];
                const float* f0 = feat + (size_t)s0 * 256 + lane * 8;
                const float* f1 = feat + (size_t)s1 * 256 + lane * 8;
                float4 p0 = *reinterpret_cast<const float4*>(f0);
                float4 p1 = *reinterpret_cast<const float4*>(f0 + 4);
                float4 q0 = *reinterpret_cast<const float4*>(f1);
                float4 q1 = *reinterpret_cast<const float4*>(f1 + 4);
                acc[0] += ee0 * p0.x; acc[1] += ee0 * p0.y;
                acc[2] += ee0 * p0.z; acc[3] += ee0 * p0.w;
                acc[4] += ee0 * p1.x; acc[5] += ee0 * p1.y;
                acc[6] += ee0 * p1.z; acc[7] += ee0 * p1.w;
                acc[0] += ee1 * q0.x; acc[1] += ee1 * q0.y;
                acc[2] += ee1 * q0.z; acc[3] += ee1 * q0.w;
                acc[4] += ee1 * q1.x; acc[5] += ee1 * q1.y;
                acc[6] += ee1 * q1.z; acc[7] += ee1 * q1.w;
            }
            if (t < cnt) {
                int s0 = sSrc[wl][t];
                float ee0 = sEE[wl][h][t];
                const float* f0 = feat + (size_t)s0 * 256 + lane * 8;
                float4 p0 = *reinterpret_cast<const float4*>(f0);
                float4 p1 = *reinterpret_cast<const float4*>(f0 + 4);
                acc[0] += ee0 * p0.x; acc[1] += ee0 * p0.y;
                acc[2] += ee0 * p0.z; acc[3] += ee0 * p0.w;
                acc[4] += ee0 * p1.x; acc[5] += ee0 * p1.y;
                acc[6] += ee0 * p1.z; acc[7] += ee0 * p1.w;
            }
        } else {
            int c0 = lane * 5;
            int h0 = c0 / 40, h1 = (c0 + 1) / 40, h2 = (c0 + 2) / 40,
                h3 = (c0 + 3) / 40, h4 = (c0 + 4) / 40;
            int t = 0;
            for (; t + 1 < cnt; t += 2) {
                int s0 = sSrc[wl][t], s1 = sSrc[wl][t + 1];
                const float* f0 = feat + (size_t)s0 * 160 + c0;
                const float* f1 = feat + (size_t)s1 * 160 + c0;
                float a0 = f0[0], a1 = f0[1], a2 = f0[2], a3 = f0[3], a4 = f0[4];
                float b0 = f1[0], b1 = f1[1], b2 = f1[2], b3 = f1[3], b4 = f1[4];
                acc[0] += sEE[wl][h0][t] * a0 + sEE[wl][h0][t + 1] * b0;
                acc[1] += sEE[wl][h1][t] * a1 + sEE[wl][h1][t + 1] * b1;
                acc[2] += sEE[wl][h2][t] * a2 + sEE[wl][h2][t + 1] * b2;
                acc[3] += sEE[wl][h3][t] * a3 + sEE[wl][h3][t + 1] * b3;
                acc[4] += sEE[wl][h4][t] * a4 + sEE[wl][h4][t + 1] * b4;
            }
            if (t < cnt) {
                int s0 = sSrc[wl][t];
                const float* f0 = feat + (size_t)s0 * 160 + c0;
                acc[0] += sEE[wl][h0][t] * f0[0];
                acc[1] += sEE[wl][h1][t] * f0[1];
                acc[2] += sEE[wl][h2][t] * f0[2];
                acc[3] += sEE[wl][h3][t] * f0[3];
                acc[4] += sEE[wl][h4][t] * f0[4];
            }
        }
        __syncwarp();
    }

#pragma unroll
    for (int h = 0; h < 4; h++) {
#pragma unroll
        for (int o = 16; o; o >>= 1)
            den[h] += __shfl_xor_sync(0xffffffffu, den[h], o);
        den[h] = fmaxf(den[h], 1e-9f);
    }

    if constexpr (MODE == 0) {
        int c0 = lane * 8;
        float inv = 1.f / den[lane >> 3];
        float o[8];
#pragma unroll
        for (int j = 0; j < 8; j++) {
            float v = acc[j] * inv + bias[c0 + j];
            o[j] = v > 0.f ? v : expm1f(v);
        }
        float* op = out + (size_t)d * 256 + c0;
        *reinterpret_cast<float4*>(op) = make_float4(o[0], o[1], o[2], o[3]);
        *reinterpret_cast<float4*>(op + 4) = make_float4(o[4], o[5], o[6], o[7]);
    } else {
        int c0 = lane * 5;
#pragma unroll
        for (int j = 0; j < 5; j++) {
            int c = c0 + j;
            sOut[wl][c] = acc[j] / den[c / 40] + bias[c];
        }
        __syncwarp();
        float* lg = out + (size_t)d * 40;
        {
            int c = lane;
            lg[c] = 0.25f * (sOut[wl][c] + sOut[wl][40 + c] + sOut[wl][80 + c] + sOut[wl][120 + c]);
        }
        if (lane < 8) {
            int c = 32 + lane;
            lg[c] = 0.25f * (sOut[wl][c] + sOut[wl][40 + c] + sOut[wl][80 + c] + sOut[wl][120 + c]);
        }
    }
}

// ---------------------------------------------------------------
extern "C" void kernel_launch(void* const* d_in, const int* in_sizes, int n_in,
                              void* d_out, int out_size) {
    const float* x  = (const float*)d_in[0];
    const int*   ei = (const int*)d_in[1];
    const float* W0  = (const float*)d_in[2];
    const float* al0 = (const float*)d_in[3];
    const float* ar0 = (const float*)d_in[4];
    const float* b0  = (const float*)d_in[5];
    const float* W1  = (const float*)d_in[6];
    const float* al1 = (const float*)d_in[7];
    const float* ar1 = (const float*)d_in[8];
    const float* b1  = (const float*)d_in[9];
    const float* W2  = (const float*)d_in[10];
    const float* al2 = (const float*)d_in[11];
    const float* ar2 = (const float*)d_in[12];
    const float* b2  = (const float*)d_in[13];

    int E = in_sizes[1] / 2;
    int N = in_sizes[0] / 256;
    const int* src = ei;
    const int* dst = ei + E;

    void* pv = nullptr;
    cudaGetSymbolAddress(&pv, g_pool);
    float* pool = (float*)pv;
    float* feat = pool;
    float* bufA = feat + (size_t)NN * 256;
    float* bufB = bufA + (size_t)NN * 256;
    float* el   = bufB + (size_t)NN * 256;
    float* er   = el + (size_t)NN * 4;

    void* iv = nullptr;
    cudaGetSymbolAddress(&iv, g_ipool);
    int* rowptr = (int*)iv;
    int* deg    = rowptr + NN + 1;
    int* cursor = deg + NN;
    int* srcS   = cursor + NN;

    const int TB = 256;
    auto blocks = [](long n, int tb) { return (int)((n + tb - 1) / tb); };

    // ---- build CSR (by dst) ----
    zero_int<<<blocks(N, TB), TB>>>(deg, N);
    hist_kernel<<<blocks(E, TB), TB>>>(dst, deg, E);
    scan_kernel<<<1, 1024>>>(deg, rowptr, cursor, N, E);
    scatter_kernel<<<blocks(E, TB), TB>>>(src, dst, cursor, srcS, E);

    int aggBlocks = (N + 7) / 8;
    int gy = (N + 127) / 128;

    // ---- layer 0 ----
    zero_f<<<blocks((long)N * 8, TB), TB>>>(el, N * 8);
    gemm_tf32<true><<<dim3(2, gy), 256>>>(x, W0, feat, N, 256, 256, al0, ar0, el, er);
    gat_aggregate<64, 0><<<aggBlocks, 256>>>(rowptr, srcS, el, er, feat, b0, bufA, N);
    // ---- layer 1 ----
    zero_f<<<blocks((long)N * 8, TB), TB>>>(el, N * 8);
    gemm_tf32<true><<<dim3(2, gy), 256>>>(bufA, W1, feat, N, 256, 256, al1, ar1, el, er);
    gat_aggregate<64, 0><<<aggBlocks, 256>>>(rowptr, srcS, el, er, feat, b1, bufB, N);
    // ---- layer 2 (HD=160) ----
    gemm_tf32<false><<<dim3(2, gy), 256>>>(bufB, W2, feat, N, 256, 160, nullptr, nullptr, nullptr, nullptr);
    el_er_kernel<<<blocks((long)N * HH * 32, TB), TB>>>(feat, al2, ar2, el, er, N, 40);
    gat_aggregate<40, 1><<<aggBlocks, 256>>>(rowptr, srcS, el, er, feat, b2, (float*)d_out, N);
}

// round 9
// speedup vs baseline: 2.9845x; 1.1158x over previous
#include <cuda_runtime.h>
#include <cuda_fp16.h>
#include <cstdint>

#define NN 50000
#define EE 800000
#define HH 4

// -------- scratch (device globals, no allocations) --------
__device__ float g_pool[(size_t)NN * 256 * 3 + (size_t)NN * 8];
__device__ __half g_hf[(size_t)NN * 256];
__device__ int g_ipool[(size_t)NN * 3 + 1 + (size_t)EE];

// -------- small utility kernels --------
__global__ void zero_int(int* p, int n) {
    int t = blockIdx.x * blockDim.x + threadIdx.x;
    if (t < n) p[t] = 0;
}
__global__ void zero_f(float* p, int n) {
    int t = blockIdx.x * blockDim.x + threadIdx.x;
    if (t < n) p[t] = 0.f;
}
__global__ void hist_kernel(const int* __restrict__ dst, int* __restrict__ deg, int E) {
    int t = blockIdx.x * blockDim.x + threadIdx.x;
    if (t < E) atomicAdd(&deg[dst[t]], 1);
}
__global__ void scan_kernel(const int* __restrict__ deg, int* __restrict__ rowptr,
                            int* __restrict__ cursor, int N, int E) {
    __shared__ int sums[1024];
    int t = threadIdx.x;
    int chunk = (N + 1023) >> 10;
    int lo = t * chunk, hi = min(N, lo + chunk);
    int s = 0;
    for (int i = lo; i < hi; i++) s += deg[i];
    sums[t] = s;
    __syncthreads();
    for (int off = 1; off < 1024; off <<= 1) {
        int v = (t >= off) ? sums[t - off] : 0;
        __syncthreads();
        sums[t] += v;
        __syncthreads();
    }
    int run = (t == 0) ? 0 : sums[t - 1];
    for (int i = lo; i < hi; i++) { rowptr[i] = run; cursor[i] = run; run += deg[i]; }
    if (lo < N && hi == N) rowptr[N] = E;
}
__global__ void scatter_kernel(const int* __restrict__ src, const int* __restrict__ dst,
                               int* __restrict__ cursor, int* __restrict__ srcSorted, int E) {
    int t = blockIdx.x * blockDim.x + threadIdx.x;
    if (t >= E) return;
    int d = dst[t];
    int pos = atomicAdd(&cursor[d], 1);
    srcSorted[pos] = src[t];
}

// -------- tf32 tensor-core GEMM, double-buffered smem --------
// 128x128 block tile, 8 warps (2x4), 64x32 warp tile = 4x4 m16n8k8 frags.
// Always writes fp16 output (Ch). WF32: also write fp32 C.
// ATT: emit el/er partials via shuffle+atomicAdd (64-wide aligned heads).
__device__ __forceinline__ unsigned f2tf32(float f) {
    unsigned r;
    asm("cvt.rna.tf32.f32 %0, %1;" : "=r"(r) : "f"(f));
    return r;
}

#define SM_STRIDE 136

template <bool ATT, bool WF32>
__global__ __launch_bounds__(256) void gemm_tf32(const float* __restrict__ A,
                                                 const float* __restrict__ B,
                                                 float* __restrict__ C,
                                                 __half* __restrict__ Ch,
                                                 int M, int K, int Ncols,
                                                 const float* __restrict__ al,
                                                 const float* __restrict__ ar,
                                                 float* __restrict__ el,
                                                 float* __restrict__ er) {
    __shared__ unsigned As[2][16][SM_STRIDE];
    __shared__ unsigned Bs[2][16][SM_STRIDE];
    int tid = threadIdx.x;
    int warp = tid >> 5, lane = tid & 31;
    int gid = lane >> 2, tig = lane & 3;
    int warp_m = warp >> 2, warp_n = warp & 3;
    int rowBase = blockIdx.y * 128;
    int colBase = blockIdx.x * 128;

    int ar_ = tid >> 1;
    int ak = (tid & 1) * 8;
    int br = tid >> 4;
    int bc = (tid & 15) * 8;

    int gr = rowBase + ar_;
    bool aOk = (gr < M);
    int gc = colBase + bc;
    bool bFull = (gc + 7 < Ncols);

    const float* aBase = A + (size_t)gr * K + ak;
    const float* bBase = B + (size_t)br * Ncols + gc;

    float acc[4][4][4];
#pragma unroll
    for (int i = 0; i < 4; i++)
#pragma unroll
        for (int j = 0; j < 4; j++)
#pragma unroll
            for (int c = 0; c < 4; c++) acc[i][j][c] = 0.f;

    const int P = K >> 4;
    float ra[8], rb[8];

    auto loadPanel = [&](int p, float* la, float* lb) {
        const float* ap = aBase + p * 16;
        const float* bp = bBase + (size_t)p * 16 * Ncols;
        if (aOk) {
            float4 a0 = *reinterpret_cast<const float4*>(ap);
            float4 a1 = *reinterpret_cast<const float4*>(ap + 4);
            la[0] = a0.x; la[1] = a0.y; la[2] = a0.z; la[3] = a0.w;
            la[4] = a1.x; la[5] = a1.y; la[6] = a1.z; la[7] = a1.w;
        } else {
#pragma unroll
            for (int i = 0; i < 8; i++) la[i] = 0.f;
        }
        if (bFull) {
            float4 b0 = *reinterpret_cast<const float4*>(bp);
            float4 b1 = *reinterpret_cast<const float4*>(bp + 4);
            lb[0] = b0.x; lb[1] = b0.y; lb[2] = b0.z; lb[3] = b0.w;
            lb[4] = b1.x; lb[5] = b1.y; lb[6] = b1.z; lb[7] = b1.w;
        } else {
#pragma unroll
            for (int j = 0; j < 8; j++)
                lb[j] = (gc + j < Ncols) ? bp[j] : 0.f;
        }
    };

    // prologue: panel 0 -> smem[0]
    loadPanel(0, ra, rb);
#pragma unroll
    for (int i = 0; i < 8; i++) As[0][ak + i][ar_] = f2tf32(ra[i]);
#pragma unroll
    for (int j = 0; j < 8; j++) Bs[0][br][bc + j] = f2tf32(rb[j]);
    __syncthreads();

    for (int p = 0; p < P; p++) {
        int cur = p & 1, nxt = cur ^ 1;
        // prefetch next panel (LDG in flight during compute)
        if (p + 1 < P) loadPanel(p + 1, ra, rb);

        // compute from smem[cur]
#pragma unroll
        for (int ks = 0; ks < 2; ks++) {
            int k0 = ks * 8;
            unsigned af[4][4], bf[4][2];
#pragma unroll
            for (int mi = 0; mi < 4; mi++) {
                int mB = warp_m * 64 + mi * 16;
                af[mi][0] = As[cur][k0 + tig][mB + gid];
                af[mi][1] = As[cur][k0 + tig][mB + gid + 8];
                af[mi][2] = As[cur][k0 + tig + 4][mB + gid];
                af[mi][3] = As[cur][k0 + tig + 4][mB + gid + 8];
            }
#pragma unroll
            for (int ni = 0; ni < 4; ni++) {
                int nB = warp_n * 32 + ni * 8;
                bf[ni][0] = Bs[cur][k0 + tig][nB + gid];
                bf[ni][1] = Bs[cur][k0 + tig + 4][nB + gid];
            }
#pragma unroll
            for (int mi = 0; mi < 4; mi++)
#pragma unroll
                for (int ni = 0; ni < 4; ni++) {
                    asm volatile(
                        "mma.sync.aligned.m16n8k8.row.col.f32.tf32.tf32.f32 "
                        "{%0,%1,%2,%3}, {%4,%5,%6,%7}, {%8,%9}, {%0,%1,%2,%3};\n"
                        : "+f"(acc[mi][ni][0]), "+f"(acc[mi][ni][1]),
                          "+f"(acc[mi][ni][2]), "+f"(acc[mi][ni][3])
                        : "r"(af[mi][0]), "r"(af[mi][1]), "r"(af[mi][2]), "r"(af[mi][3]),
                          "r"(bf[ni][0]), "r"(bf[ni][1]));
                }
        }

        if (p + 1 < P) {
#pragma unroll
            for (int i = 0; i < 8; i++) As[nxt][ak + i][ar_] = f2tf32(ra[i]);
#pragma unroll
            for (int j = 0; j < 8; j++) Bs[nxt][br][bc + j] = f2tf32(rb[j]);
            __syncthreads();
        }
    }

    // store outputs
#pragma unroll
    for (int mi = 0; mi < 4; mi++) {
        int r0 = rowBase + warp_m * 64 + mi * 16 + gid;
#pragma unroll
        for (int ni = 0; ni < 4; ni++) {
            int c0 = colBase + warp_n * 32 + ni * 8 + tig * 2;
            if (c0 < Ncols) {
                if (r0 < M) {
                    *reinterpret_cast<__half2*>(&Ch[(size_t)r0 * Ncols + c0]) =
                        __floats2half2_rn(acc[mi][ni][0], acc[mi][ni][1]);
                    if (WF32)
                        *reinterpret_cast<float2*>(&C[(size_t)r0 * Ncols + c0]) =
                            make_float2(acc[mi][ni][0], acc[mi][ni][1]);
                }
                if (r0 + 8 < M) {
                    *reinterpret_cast<__half2*>(&Ch[(size_t)(r0 + 8) * Ncols + c0]) =
                        __floats2half2_rn(acc[mi][ni][2], acc[mi][ni][3]);
                    if (WF32)
                        *reinterpret_cast<float2*>(&C[(size_t)(r0 + 8) * Ncols + c0]) =
                            make_float2(acc[mi][ni][2], acc[mi][ni][3]);
                }
            }
        }
    }

    // fused el/er partials (heads 64 cols wide; warp's cols lie in one head)
    if (ATT) {
        int h = (colBase + warp_n * 32) >> 6;
#pragma unroll
        for (int mi = 0; mi < 4; mi++) {
            float pl0 = 0.f, pl1 = 0.f, pr0 = 0.f, pr1 = 0.f;
#pragma unroll
            for (int ni = 0; ni < 4; ni++) {
#pragma unroll
                for (int j = 0; j < 2; j++) {
                    int cw = (colBase + warp_n * 32 + ni * 8 + tig * 2 + j) & 63;
                    float av = al[h * 64 + cw];
                    float rv = ar[h * 64 + cw];
                    pl0 += acc[mi][ni][j] * av;
                    pr0 += acc[mi][ni][j] * rv;
                    pl1 += acc[mi][ni][2 + j] * av;
                    pr1 += acc[mi][ni][2 + j] * rv;
                }
            }
#pragma unroll
            for (int o = 1; o <= 2; o <<= 1) {
                pl0 += __shfl_xor_sync(0xffffffffu, pl0, o);
                pr0 += __shfl_xor_sync(0xffffffffu, pr0, o);
                pl1 += __shfl_xor_sync(0xffffffffu, pl1, o);
                pr1 += __shfl_xor_sync(0xffffffffu, pr1, o);
            }
            if (tig == 0) {
                int r0 = rowBase + warp_m * 64 + mi * 16 + gid;
                if (r0 < M) {
                    atomicAdd(&el[r0 * 4 + h], pl0);
                    atomicAdd(&er[r0 * 4 + h], pr0);
                }
                if (r0 + 8 < M) {
                    atomicAdd(&el[(r0 + 8) * 4 + h], pl1);
                    atomicAdd(&er[(r0 + 8) * 4 + h], pr1);
                }
            }
        }
    }
}

// -------- el/er for layer 2 (D=40, unaligned heads) — fp32 feat --------
__global__ void el_er_kernel(const float* __restrict__ feat,
                             const float* __restrict__ al, const float* __restrict__ ar,
                             float* __restrict__ el, float* __restrict__ er,
                             int N, int D) {
    int w = (blockIdx.x * blockDim.x + threadIdx.x) >> 5;
    int lane = threadIdx.x & 31;
    if (w >= N * HH) return;
    int n = w / HH, h = w - n * HH;
    const float* f = feat + (size_t)n * HH * D + h * D;
    float sl = 0.f, sr = 0.f;
    for (int d = lane; d < D; d += 32) {
        float fv = f[d];
        sl += fv * al[h * D + d];
        sr += fv * ar[h * D + d];
    }
#pragma unroll
    for (int o = 16; o; o >>= 1) {
        sl += __shfl_down_sync(0xffffffffu, sl, o);
        sr += __shfl_down_sync(0xffffffffu, sr, o);
    }
    if (lane == 0) { el[w] = sl; er[w] = sr; }
}

// 8 fp16 channels (uint4) fma into fp32 acc
__device__ __forceinline__ void hf8_fma(float* acc, uint4 u, float ee) {
    float2 f;
    f = __half22float2(*reinterpret_cast<__half2*>(&u.x));
    acc[0] += ee * f.x; acc[1] += ee * f.y;
    f = __half22float2(*reinterpret_cast<__half2*>(&u.y));
    acc[2] += ee * f.x; acc[3] += ee * f.y;
    f = __half22float2(*reinterpret_cast<__half2*>(&u.z));
    acc[4] += ee * f.x; acc[5] += ee * f.y;
    f = __half22float2(*reinterpret_cast<__half2*>(&u.w));
    acc[6] += ee * f.x; acc[7] += ee * f.y;
}

// -------- fused softmax + aggregation: one warp per dst node --------
// fp16 feature gather (8 channels/lane via LDG.128), fp32 accumulate.
// MODE 0: D=64, all 32 lanes, out[d,256] = elu(acc/den + bias)
// MODE 1: D=40, lanes 0..19, out = logits[d,40] = mean_h(acc/den + bias)
template <int D, int MODE>
__global__ __launch_bounds__(256) void gat_aggregate(
    const int* __restrict__ rowptr, const int* __restrict__ srcS,
    const float* __restrict__ el, const float* __restrict__ er,
    const __half* __restrict__ hfeat, const float* __restrict__ bias,
    float* __restrict__ out, int N) {
    constexpr int HD = 4 * D;
    __shared__ float sEE[8][4][32];
    __shared__ int sSrc[8][32];
    __shared__ float sOut[MODE == 1 ? 8 : 1][MODE == 1 ? 160 : 1];
    int wl = threadIdx.x >> 5, lane = threadIdx.x & 31;
    int d = blockIdx.x * 8 + wl;
    if (d >= N) return;
    int begin = rowptr[d], end = rowptr[d + 1];

    float4 erv = *reinterpret_cast<const float4*>(&er[d * 4]);
    float er4[4] = {erv.x, erv.y, erv.z, erv.w};

    float m[4] = {-1e30f, -1e30f, -1e30f, -1e30f};
    for (int i = begin + lane; i < end; i += 32) {
        int s = srcS[i];
        float4 e4 = *reinterpret_cast<const float4*>(&el[s * 4]);
        float v;
        v = e4.x + er4[0]; v = v > 0.f ? v : 0.2f * v; m[0] = fmaxf(m[0], v);
        v = e4.y + er4[1]; v = v > 0.f ? v : 0.2f * v; m[1] = fmaxf(m[1], v);
        v = e4.z + er4[2]; v = v > 0.f ? v : 0.2f * v; m[2] = fmaxf(m[2], v);
        v = e4.w + er4[3]; v = v > 0.f ? v : 0.2f * v; m[3] = fmaxf(m[3], v);
    }
#pragma unroll
    for (int h = 0; h < 4; h++)
#pragma unroll
        for (int o = 16; o; o >>= 1)
            m[h] = fmaxf(m[h], __shfl_xor_sync(0xffffffffu, m[h], o));

    float acc[8];
#pragma unroll
    for (int j = 0; j < 8; j++) acc[j] = 0.f;
    float den[4] = {0.f, 0.f, 0.f, 0.f};

    const int h = (MODE == 0) ? (lane >> 3) : (lane / 5);
    const bool active = (MODE == 0) ? true : (lane < 20);
    const int cOff = lane * 8;

    for (int base = begin; base < end; base += 32) {
        int cnt = min(32, end - base);
        if (lane < cnt) {
            int s = srcS[base + lane];
            sSrc[wl][lane] = s;
            float4 e4 = *reinterpret_cast<const float4*>(&el[s * 4]);
            float v, ee;
            v = e4.x + er4[0]; v = v > 0.f ? v : 0.2f * v; ee = __expf(v - m[0]); den[0] += ee; sEE[wl][0][lane] = ee;
            v = e4.y + er4[1]; v = v > 0.f ? v : 0.2f * v; ee = __expf(v - m[1]); den[1] += ee; sEE[wl][1][lane] = ee;
            v = e4.z + er4[2]; v = v > 0.f ? v : 0.2f * v; ee = __expf(v - m[2]); den[2] += ee; sEE[wl][2][lane] = ee;
            v = e4.w + er4[3]; v = v > 0.f ? v : 0.2f * v; ee = __expf(v - m[3]); den[3] += ee; sEE[wl][3][lane] = ee;
        }
        __syncwarp();

        if (active) {
            int t = 0;
            for (; t + 3 < cnt; t += 4) {
                int s0 = sSrc[wl][t], s1 = sSrc[wl][t + 1], s2 = sSrc[wl][t + 2], s3 = sSrc[wl][t + 3];
                uint4 u0 = *reinterpret_cast<const uint4*>(hfeat + (size_t)s0 * HD + cOff);
                uint4 u1 = *reinterpret_cast<const uint4*>(hfeat + (size_t)s1 * HD + cOff);
                uint4 u2 = *reinterpret_cast<const uint4*>(hfeat + (size_t)s2 * HD + cOff);
                uint4 u3 = *reinterpret_cast<const uint4*>(hfeat + (size_t)s3 * HD + cOff);
                hf8_fma(acc, u0, sEE[wl][h][t]);
                hf8_fma(acc, u1, sEE[wl][h][t + 1]);
                hf8_fma(acc, u2, sEE[wl][h][t + 2]);
                hf8_fma(acc, u3, sEE[wl][h][t + 3]);
            }
            for (; t < cnt; t++) {
                int s0 = sSrc[wl][t];
                uint4 u0 = *reinterpret_cast<const uint4*>(hfeat + (size_t)s0 * HD + cOff);
                hf8_fma(acc, u0, sEE[wl][h][t]);
            }
        }
        __syncwarp();
    }

#pragma unroll
    for (int hh = 0; hh < 4; hh++) {
#pragma unroll
        for (int o = 16; o; o >>= 1)
            den[hh] += __shfl_xor_sync(0xffffffffu, den[hh], o);
        den[hh] = fmaxf(den[hh], 1e-9f);
    }

    if constexpr (MODE == 0) {
        float inv = 1.f / den[h];
        float o[8];
#pragma unroll
        for (int j = 0; j < 8; j++) {
            float v = acc[j] * inv + bias[cOff + j];
            o[j] = v > 0.f ? v : expm1f(v);
        }
        float* op = out + (size_t)d * 256 + cOff;
        *reinterpret_cast<float4*>(op) = make_float4(o[0], o[1], o[2], o[3]);
        *reinterpret_cast<float4*>(op + 4) = make_float4(o[4], o[5], o[6], o[7]);
    } else {
        if (active) {
            float inv = 1.f / den[h];
#pragma unroll
            for (int j = 0; j < 8; j++)
                sOut[wl][cOff + j] = acc[j] * inv + bias[cOff + j];
        }
        __syncwarp();
        float* lg = out + (size_t)d * 40;
        {
            int c = lane;
            lg[c] = 0.25f * (sOut[wl][c] + sOut[wl][40 + c] + sOut[wl][80 + c] + sOut[wl][120 + c]);
        }
        if (lane < 8) {
            int c = 32 + lane;
            lg[c] = 0.25f * (sOut[wl][c] + sOut[wl][40 + c] + sOut[wl][80 + c] + sOut[wl][120 + c]);
        }
    }
}

// ---------------------------------------------------------------
extern "C" void kernel_launch(void* const* d_in, const int* in_sizes, int n_in,
                              void* d_out, int out_size) {
    const float* x  = (const float*)d_in[0];
    const int*   ei = (const int*)d_in[1];
    const float* W0  = (const float*)d_in[2];
    const float* al0 = (const float*)d_in[3];
    const float* ar0 = (const float*)d_in[4];
    const float* b0  = (const float*)d_in[5];
    const float* W1  = (const float*)d_in[6];
    const float* al1 = (const float*)d_in[7];
    const float* ar1 = (const float*)d_in[8];
    const float* b1  = (const float*)d_in[9];
    const float* W2  = (const float*)d_in[10];
    const float* al2 = (const float*)d_in[11];
    const float* ar2 = (const float*)d_in[12];
    const float* b2  = (const float*)d_in[13];

    int E = in_sizes[1] / 2;
    int N = in_sizes[0] / 256;
    const int* src = ei;
    const int* dst = ei + E;

    void* pv = nullptr;
    cudaGetSymbolAddress(&pv, g_pool);
    float* pool = (float*)pv;
    float* feat = pool;                              // fp32 feat (layer 2 only)
    float* bufA = feat + (size_t)NN * 256;
    float* bufB = bufA + (size_t)NN * 256;
    float* el   = bufB + (size_t)NN * 256;
    float* er   = el + (size_t)NN * 4;

    void* hv = nullptr;
    cudaGetSymbolAddress(&hv, g_hf);
    __half* hfeat = (__half*)hv;

    void* iv = nullptr;
    cudaGetSymbolAddress(&iv, g_ipool);
    int* rowptr = (int*)iv;
    int* deg    = rowptr + NN + 1;
    int* cursor = deg + NN;
    int* srcS   = cursor + NN;

    const int TB = 256;
    auto blocks = [](long n, int tb) { return (int)((n + tb - 1) / tb); };

    // ---- build CSR (by dst) ----
    zero_int<<<blocks(N, TB), TB>>>(deg, N);
    hist_kernel<<<blocks(E, TB), TB>>>(dst, deg, E);
    scan_kernel<<<1, 1024>>>(deg, rowptr, cursor, N, E);
    scatter_kernel<<<blocks(E, TB), TB>>>(src, dst, cursor, srcS, E);

    int aggBlocks = (N + 7) / 8;
    int gy = (N + 127) / 128;

    // ---- layer 0 ----
    zero_f<<<blocks((long)N * 8, TB), TB>>>(el, N * 8);
    gemm_tf32<true, false><<<dim3(2, gy), 256>>>(x, W0, nullptr, hfeat, N, 256, 256, al0, ar0, el, er);
    gat_aggregate<64, 0><<<aggBlocks, 256>>>(rowptr, srcS, el, er, hfeat, b0, bufA, N);
    // ---- layer 1 ----
    zero_f<<<blocks((long)N * 8, TB), TB>>>(el, N * 8);
    gemm_tf32<true, false><<<dim3(2, gy), 256>>>(bufA, W1, nullptr, hfeat, N, 256, 256, al1, ar1, el, er);
    gat_aggregate<64, 0><<<aggBlocks, 256>>>(rowptr, srcS, el, er, hfeat, b1, bufB, N);
    // ---- layer 2 (HD=160) ----
    gemm_tf32<false, true><<<dim3(2, gy), 256>>>(bufB, W2, feat, hfeat, N, 256, 160, nullptr, nullptr, nullptr, nullptr);
    el_er_kernel<<<blocks((long)N * HH * 32, TB), TB>>>(feat, al2, ar2, el, er, N, 40);
    gat_aggregate<40, 1><<<aggBlocks, 256>>>(rowptr, srcS, el, er, hfeat, b2, (float*)d_out, N);
}